// round 15
// baseline (speedup 1.0000x reference)
#include <cuda_runtime.h>
#include <cstdint>
#include <limits.h>

// Problem constants (fixed by the dataset)
#define MAXN 100000
#define MAXE 1600000
#define DIN  128
#define HH   8
#define D1   64   // H*C1
#define D2   80   // H*C2

typedef unsigned long long ull;

// ---------------- scratch (device globals; no allocation allowed) -------------
__device__ __align__(16) float g_h1 [MAXN * D1];
__device__ __align__(16) float g_as1[MAXN * HH];
__device__ __align__(16) float g_ad1[MAXN * HH];
__device__ __align__(16) float g_z1 [MAXN * D1];
__device__ __align__(16) float g_h2 [MAXN * D2];
__device__ __align__(16) float g_as2[MAXN * HH];
__device__ __align__(16) float g_ad2[MAXN * HH];
// CSR scratch
__device__ int g_deg [MAXN];
__device__ int g_rp  [MAXN + 1];
__device__ int g_cur [MAXN];
__device__ int g_csr [MAXE];
__device__ int g_is64;
// decoupled-lookback scan state
__device__ int g_flag[128];
__device__ int g_agg [128];
__device__ int g_pref[128];

// ---------------- helpers ----------------------------------------------------
__device__ __forceinline__ int load_dst(const void* ei, long long t, long long E) {
    if (g_is64) return (int)((const long long*)ei)[E + t];
    return ((const int*)ei)[E + t];
}
__device__ __forceinline__ int load_src(const void* ei, long long t) {
    if (g_is64) return (int)((const long long*)ei)[t];
    return ((const int*)ei)[t];
}

// Blackwell packed f32x2 FMA (ptxas only emits FFMA2 via PTX fma.rn.f32x2)
__device__ __forceinline__ ull pack2(float x) {
    ull r; asm("mov.b64 %0, {%1, %1};" : "=l"(r) : "f"(x)); return r;
}
__device__ __forceinline__ void ffma2(ull& d, ull a, ull b) {
    asm("fma.rn.f32x2 %0, %1, %2, %0;" : "+l"(d) : "l"(a), "l"(b));
}
__device__ __forceinline__ float2 unpack2(ull v) {
    float lo, hi; asm("mov.b64 {%0, %1}, %2;" : "=f"(lo), "=f"(hi) : "l"(v));
    return make_float2(lo, hi);
}
__device__ __forceinline__ float lrelu_exp(float v) {
    float e = v > 0.f ? v : 0.2f * v;
    return __expf(e);
}

// ---------------- CSR build ---------------------------------------------------

// Detect int64 vs int32 + zero degree array + zero scan flags (fused).
__global__ void k_init(const unsigned* __restrict__ ei, int n) {
    int i = blockIdx.x * blockDim.x + threadIdx.x;
    if (i == 0) {
        int zeros = 0;
        for (int j = 0; j < 64; j++)
            if (ei[2 * j + 1] == 0u) zeros++;
        g_is64 = (zeros >= 60) ? 1 : 0;
    }
    if (i < 128) g_flag[i] = 0;
    if (i < n) g_deg[i] = 0;
}

// Heterogeneous kernel: first gtiles blocks run gemm1 (64x64 tile, FFMA2),
// remaining blocks histogram edge destinations (hidden behind the gemm).
__global__ void __launch_bounds__(256) k_gemm1_hist(
        const float* __restrict__ x, const float* __restrict__ W1,
        const float* __restrict__ asrc, const float* __restrict__ adst, int n,
        const void* __restrict__ ei, long long E, int gtiles) {
    if ((int)blockIdx.x >= gtiles) {
        long long t = (long long)(blockIdx.x - gtiles) * 256 + threadIdx.x;
        if (t < E) atomicAdd(&g_deg[load_dst(ei, t, E)], 1);
        return;
    }
    __shared__ __align__(16) float Ws[DIN * D1];   // [k][col] 32 KB
    __shared__ __align__(16) float xs[64][132];    // padded: banks rotate, f4-aligned
    __shared__ float av[2][D1];
    int tid = threadIdx.x;
    for (int i = tid; i < DIN * D1 / 4; i += 256)
        *(float4*)(Ws + 4 * i) = *(const float4*)(W1 + 4 * i);
    if (tid < D1) { av[0][tid] = asrc[tid]; av[1][tid] = adst[tid]; }

    int n0 = blockIdx.x * 64;
    for (int i = tid; i < 64 * 32; i += 256) {
        int r = i >> 5, c4 = i & 31;
        int nd = n0 + r;
        float4 v = (nd < n) ? *(const float4*)(x + (size_t)nd * DIN + 4 * c4)
                            : make_float4(0.f, 0.f, 0.f, 0.f);
        *(float4*)&xs[r][4 * c4] = v;
    }
    __syncthreads();

    int cg = tid & 15, rg = tid >> 4;
    int c0 = cg * 4, r0 = rg * 4;
    ull acc[4][2] = {};
    #pragma unroll 8
    for (int k = 0; k < DIN; k++) {
        ulonglong2 w = *(const ulonglong2*)(Ws + k * D1 + c0);
        #pragma unroll
        for (int i = 0; i < 4; i++) {
            ull xp = pack2(xs[r0 + i][k]);
            ffma2(acc[i][0], xp, w.x);
            ffma2(acc[i][1], xp, w.y);
        }
    }

    float h[4][4];
    #pragma unroll
    for (int i = 0; i < 4; i++) {
        float2 lo = unpack2(acc[i][0]), hi = unpack2(acc[i][1]);
        h[i][0] = lo.x; h[i][1] = lo.y; h[i][2] = hi.x; h[i][3] = hi.y;
    }
    float ps[4], pd[4];
    #pragma unroll
    for (int i = 0; i < 4; i++) {
        float s = 0.f, d = 0.f;
        #pragma unroll
        for (int j = 0; j < 4; j++) {
            s += h[i][j] * av[0][c0 + j];
            d += h[i][j] * av[1][c0 + j];
        }
        ps[i] = s; pd[i] = d;
    }
    #pragma unroll
    for (int i = 0; i < 4; i++) {
        ps[i] += __shfl_xor_sync(0xffffffffu, ps[i], 1);
        pd[i] += __shfl_xor_sync(0xffffffffu, pd[i], 1);
    }
    #pragma unroll
    for (int i = 0; i < 4; i++) {
        int nd = n0 + r0 + i;
        if (nd < n) {
            *(float4*)(g_h1 + (size_t)nd * D1 + c0) =
                make_float4(h[i][0], h[i][1], h[i][2], h[i][3]);
            if (!(cg & 1))
                { g_as1[(size_t)nd * 8 + (cg >> 1)] = ps[i];
                  g_ad1[(size_t)nd * 8 + (cg >> 1)] = pd[i]; }
        }
    }
}

// Single-pass decoupled-lookback scan of g_deg -> g_rp/g_cur.
__global__ void __launch_bounds__(1024) k_scan(int n, int E) {
    __shared__ int s[1024];
    __shared__ int s_run;
    int b = blockIdx.x;
    int i = b * 1024 + threadIdx.x;
    int v = (i < n) ? g_deg[i] : 0;
    s[threadIdx.x] = v;
    __syncthreads();
    #pragma unroll
    for (int off = 1; off < 1024; off <<= 1) {
        int t = (threadIdx.x >= off) ? s[threadIdx.x - off] : 0;
        __syncthreads();
        s[threadIdx.x] += t;
        __syncthreads();
    }
    int total = s[1023];

    if (threadIdx.x == 0) {
        if (b == 0) {
            g_pref[0] = total;
            __threadfence();
            g_flag[0] = 2;
            s_run = 0;
            g_rp[n] = E;
        } else {
            g_agg[b] = total;
            __threadfence();
            g_flag[b] = 1;
            int run = 0, p = b - 1;
            while (true) {
                int f;
                do { f = *(volatile int*)&g_flag[p]; } while (f == 0);
                __threadfence();
                if (f == 2) { run += *(volatile int*)&g_pref[p]; break; }
                run += *(volatile int*)&g_agg[p];
                p--;
            }
            g_pref[b] = run + total;
            __threadfence();
            g_flag[b] = 2;
            s_run = run;
        }
    }
    __syncthreads();
    if (i < n) {
        int e = s_run + s[threadIdx.x] - v;   // exclusive prefix
        g_rp[i] = e;
        g_cur[i] = e;
    }
}

__global__ void k_scatter(const void* __restrict__ ei, long long E) {
    long long t = (long long)blockIdx.x * blockDim.x + threadIdx.x;
    if (t >= E) return;
    int s = load_src(ei, t);
    int d = load_dst(ei, t, E);
    int pos = atomicAdd(&g_cur[d], 1);
    g_csr[pos] = s;
}

// ---------------- layer-2 GEMM + fused alpha2 ----------------------------------

// h2 = z1 @ W2, tile 64 nodes x 80 cols; thread = 4 rows x 4 cols (320 threads).
// Mainloop identical to the validated 320-thread version; epilogue additionally
// computes alpha_s2/alpha_d2 from an smem h tile (kills k_alpha2 + h2 re-read).
__global__ void __launch_bounds__(320) k_gemm2(
        const float* __restrict__ W2,
        const float* __restrict__ asrc, const float* __restrict__ adst, int n) {
    __shared__ __align__(16) float Ws[D1 * D2];    // 20 KB
    __shared__ __align__(16) float zs[64][68];     // 17.4 KB
    __shared__ __align__(16) float hs[64][80];     // 20 KB
    __shared__ float avs[D2], avd[D2];
    int tid = threadIdx.x;
    for (int i = tid; i < D1 * D2 / 4; i += 320)
        *(float4*)(Ws + 4 * i) = *(const float4*)(W2 + 4 * i);
    if (tid < D2) { avs[tid] = asrc[tid]; avd[tid] = adst[tid]; }
    int n0 = blockIdx.x * 64;
    for (int i = tid; i < 64 * 16; i += 320) {
        int r = i >> 4, c4 = i & 15;
        int nd = n0 + r;
        float4 v = (nd < n) ? *(const float4*)(g_z1 + (size_t)nd * D1 + 4 * c4)
                            : make_float4(0.f, 0.f, 0.f, 0.f);
        *(float4*)&zs[r][4 * c4] = v;
    }
    __syncthreads();

    int cg = tid % 20, rg = tid / 20;
    int c0 = cg * 4, r0 = rg * 4;
    ull acc[4][2] = {};
    #pragma unroll 8
    for (int k = 0; k < D1; k++) {
        ulonglong2 w = *(const ulonglong2*)(Ws + k * D2 + c0);
        #pragma unroll
        for (int i = 0; i < 4; i++) {
            ull xp = pack2(zs[r0 + i][k]);
            ffma2(acc[i][0], xp, w.x);
            ffma2(acc[i][1], xp, w.y);
        }
    }
    #pragma unroll
    for (int i = 0; i < 4; i++) {
        int r = r0 + i;
        int nd = n0 + r;
        float2 lo = unpack2(acc[i][0]), hi = unpack2(acc[i][1]);
        float4 hv = make_float4(lo.x, lo.y, hi.x, hi.y);
        *(float4*)&hs[r][c0] = hv;
        if (nd < n)
            *(float4*)(g_h2 + (size_t)nd * D2 + c0) = hv;
    }
    __syncthreads();

    // alpha epilogue: 64 rows x 8 heads = 512 tasks
    for (int t = tid; t < 512; t += 320) {
        int r = t >> 3, hd = t & 7;
        int nd = n0 + r;
        if (nd >= n) continue;
        float s = 0.f, d = 0.f;
        #pragma unroll
        for (int c = 0; c < 10; c++) {
            float v = hs[r][hd * 10 + c];
            s += v * avs[hd * 10 + c];
            d += v * avd[hd * 10 + c];
        }
        g_as2[(size_t)nd * 8 + hd] = s;
        g_ad2[(size_t)nd * 8 + hd] = d;
    }
}

// ---------------- CSR aggregation (warp per node, no atomics) ------------------
// Softmax without max-shift: exp(e)/sum(exp(e)) — safe, |logits| ~ O(1).
// Weight phase: 2 lanes per edge (even lane = alpha[0:4], odd = alpha[4:8] of the
// SAME edge) -> one coalesced wavefront per edge instead of two.

__global__ void k_agg1(const float* __restrict__ b1, int n) {
    __shared__ float wbuf[8][32][8];   // 8 KB
    __shared__ int   sbuf[8][32];      // 1 KB
    __shared__ float dbuf[8][8];
    int wid  = (blockIdx.x * blockDim.x + threadIdx.x) >> 5;
    int lane = threadIdx.x & 31;
    int wl   = threadIdx.x >> 5;
    if (wid >= n) return;
    int start = g_rp[wid], deg = g_rp[wid + 1] - start;
    int total = deg + 1;   // + self-loop
    int half = lane & 1;
    float4 adh = *(const float4*)(g_ad1 + (size_t)wid * 8 + half * 4);
    float4 den4 = make_float4(0.f, 0.f, 0.f, 0.f);
    float acc0 = 0.f, acc1 = 0.f;
    int head = lane >> 2;              // head of channels 2*lane, 2*lane+1
    for (int c0 = 0; c0 < total; c0 += 32) {
        int cnt = min(32, total - c0);
        #pragma unroll
        for (int j = 0; j < 2; j++) {
            int eo = j * 16 + (lane >> 1);
            int ew = c0 + eo;
            if (eo < cnt) {
                int s = (ew < deg) ? g_csr[start + ew] : wid;
                if (!half) sbuf[wl][eo] = s;
                float4 a = *(const float4*)(g_as1 + (size_t)s * 8 + half * 4);
                float4 w4;
                w4.x = lrelu_exp(a.x + adh.x);
                w4.y = lrelu_exp(a.y + adh.y);
                w4.z = lrelu_exp(a.z + adh.z);
                w4.w = lrelu_exp(a.w + adh.w);
                den4.x += w4.x; den4.y += w4.y; den4.z += w4.z; den4.w += w4.w;
                *(float4*)&wbuf[wl][eo][half * 4] = w4;
            }
        }
        __syncwarp();
        #pragma unroll 8
        for (int k = 0; k < cnt; k++) {
            int s = sbuf[wl][k];
            float2 hv = *(const float2*)(g_h1 + (size_t)s * D1 + 2 * lane);
            float w = wbuf[wl][k][head];
            acc0 += hv.x * w;
            acc1 += hv.y * w;
        }
        __syncwarp();
    }
    // den: xor offsets 16..2 preserve parity; even lanes hold heads 0-3, odd 4-7
    #pragma unroll
    for (int o = 16; o >= 2; o >>= 1) {
        den4.x += __shfl_xor_sync(0xffffffffu, den4.x, o);
        den4.y += __shfl_xor_sync(0xffffffffu, den4.y, o);
        den4.z += __shfl_xor_sync(0xffffffffu, den4.z, o);
        den4.w += __shfl_xor_sync(0xffffffffu, den4.w, o);
    }
    if (lane < 2) *(float4*)&dbuf[wl][half * 4] = den4;
    __syncwarp();
    float inv = 1.f / dbuf[wl][head];
    float v0 = acc0 * inv + b1[2 * lane];
    float v1 = acc1 * inv + b1[2 * lane + 1];
    v0 = v0 > 0.f ? v0 : expm1f(v0);
    v1 = v1 > 0.f ? v1 : expm1f(v1);
    *(float2*)(g_z1 + (size_t)wid * D1 + 2 * lane) = make_float2(v0, v1);
}

// Layer-2 aggregation + mean-over-heads + bias + log_softmax, fused.
__global__ void k_agg2(const float* __restrict__ b2, float* __restrict__ out, int n) {
    __shared__ float wbuf[8][32][8];
    __shared__ int   sbuf[8][32];
    __shared__ float dbuf[8][8];
    __shared__ float fb[8][80];
    int wid  = (blockIdx.x * blockDim.x + threadIdx.x) >> 5;
    int lane = threadIdx.x & 31;
    int wl   = threadIdx.x >> 5;
    if (wid >= n) return;
    int start = g_rp[wid], deg = g_rp[wid + 1] - start;
    int total = deg + 1;
    int half = lane & 1;
    float4 adh = *(const float4*)(g_ad2 + (size_t)wid * 8 + half * 4);
    float4 den4 = make_float4(0.f, 0.f, 0.f, 0.f);
    float acc0 = 0.f, acc1 = 0.f, acc2 = 0.f;
    int ha = (2 * lane) / 10;          // head of channels 2*lane, 2*lane+1
    int hc = (64 + lane) / 10;         // head of channel 64+lane (lane<16)
    for (int c0 = 0; c0 < total; c0 += 32) {
        int cnt = min(32, total - c0);
        #pragma unroll
        for (int j = 0; j < 2; j++) {
            int eo = j * 16 + (lane >> 1);
            int ew = c0 + eo;
            if (eo < cnt) {
                int s = (ew < deg) ? g_csr[start + ew] : wid;
                if (!half) sbuf[wl][eo] = s;
                float4 a = *(const float4*)(g_as2 + (size_t)s * 8 + half * 4);
                float4 w4;
                w4.x = lrelu_exp(a.x + adh.x);
                w4.y = lrelu_exp(a.y + adh.y);
                w4.z = lrelu_exp(a.z + adh.z);
                w4.w = lrelu_exp(a.w + adh.w);
                den4.x += w4.x; den4.y += w4.y; den4.z += w4.z; den4.w += w4.w;
                *(float4*)&wbuf[wl][eo][half * 4] = w4;
            }
        }
        __syncwarp();
        #pragma unroll 8
        for (int k = 0; k < cnt; k++) {
            int s = sbuf[wl][k];
            const float* hrow = g_h2 + (size_t)s * D2;
            float2 hv = *(const float2*)(hrow + 2 * lane);
            float wa = wbuf[wl][k][ha];
            acc0 += hv.x * wa;
            acc1 += hv.y * wa;
            if (lane < 16) {
                float hv2 = hrow[64 + lane];
                acc2 += hv2 * wbuf[wl][k][hc];
            }
        }
        __syncwarp();
    }
    #pragma unroll
    for (int o = 16; o >= 2; o >>= 1) {
        den4.x += __shfl_xor_sync(0xffffffffu, den4.x, o);
        den4.y += __shfl_xor_sync(0xffffffffu, den4.y, o);
        den4.z += __shfl_xor_sync(0xffffffffu, den4.z, o);
        den4.w += __shfl_xor_sync(0xffffffffu, den4.w, o);
    }
    if (lane < 2) *(float4*)&dbuf[wl][half * 4] = den4;
    __syncwarp();

    // scaled messages -> smem
    float inv_a = 1.f / dbuf[wl][ha];
    fb[wl][2 * lane]     = acc0 * inv_a;
    fb[wl][2 * lane + 1] = acc1 * inv_a;
    if (lane < 16) fb[wl][64 + lane] = acc2 / dbuf[wl][hc];
    __syncwarp();

    // mean over heads + bias + log_softmax (classes on lanes 0..9)
    float mval = -1e30f, mcls = 0.f;
    if (lane < 10) {
        float s = 0.f;
        #pragma unroll
        for (int h = 0; h < 8; h++) s += fb[wl][h * 10 + lane];
        mcls = s * 0.125f + b2[lane];
        mval = mcls;
    }
    #pragma unroll
    for (int o = 8; o >= 1; o >>= 1)
        mval = fmaxf(mval, __shfl_down_sync(0xffffffffu, mval, o));
    float mx = __shfl_sync(0xffffffffu, mval, 0);
    float ev = (lane < 10) ? __expf(mcls - mx) : 0.f;
    #pragma unroll
    for (int o = 8; o >= 1; o >>= 1)
        ev += __shfl_down_sync(0xffffffffu, ev, o);
    float lse = mx + __logf(__shfl_sync(0xffffffffu, ev, 0));
    if (lane < 10) out[(size_t)wid * 10 + lane] = mcls - lse;
}

// ---------------- launch ------------------------------------------------------
extern "C" void kernel_launch(void* const* d_in, const int* in_sizes, int n_in,
                              void* d_out, int out_size) {
    const float* x     = (const float*)d_in[0];
    const void*  ei    = d_in[1];
    const float* W1    = (const float*)d_in[2];
    const float* asrc1 = (const float*)d_in[3];
    const float* adst1 = (const float*)d_in[4];
    const float* b1    = (const float*)d_in[5];
    const float* W2    = (const float*)d_in[6];
    const float* asrc2 = (const float*)d_in[7];
    const float* adst2 = (const float*)d_in[8];
    const float* b2    = (const float*)d_in[9];
    float* out = (float*)d_out;

    int n = in_sizes[0] / DIN;                 // 100000
    long long E = (long long)in_sizes[1] / 2;  // 1600000
    int eb = (int)((E + 255) / 256);
    int nb = (n + 1023) / 1024;
    int tiles = (n + 63) / 64;

    // CSR build (+ gemm1 hidden behind hist)
    k_init<<<(n + 255) / 256, 256>>>((const unsigned*)ei, n);
    k_gemm1_hist<<<tiles + eb, 256>>>(x, W1, asrc1, adst1, n, ei, E, tiles);
    k_scan<<<nb, 1024>>>(n, (int)E);
    k_scatter<<<eb, 256>>>(ei, E);

    // Layer 1
    k_agg1<<<(n + 7) / 8, 256>>>(b1, n);

    // Layer 2 (alpha2 fused into gemm2)
    k_gemm2<<<tiles, 320>>>(W2, asrc2, adst2, n);
    k_agg2<<<(n + 7) / 8, 256>>>(b2, out, n);
}

// round 16
// speedup vs baseline: 1.0018x; 1.0018x over previous
#include <cuda_runtime.h>
#include <cstdint>
#include <limits.h>

// Problem constants (fixed by the dataset)
#define MAXN 100000
#define MAXE 1600000
#define DIN  128
#define HH   8
#define D1   64   // H*C1
#define D2   80   // H*C2

typedef unsigned long long ull;

// ---------------- scratch (device globals; no allocation allowed) -------------
__device__ __align__(16) float g_h1 [MAXN * D1];
__device__ __align__(16) float g_as1[MAXN * HH];
__device__ __align__(16) float g_ad1[MAXN * HH];
__device__ __align__(16) float g_z1 [MAXN * D1];
__device__ __align__(16) float g_h2 [MAXN * D2];
__device__ __align__(16) float g_as2[MAXN * HH];
__device__ __align__(16) float g_ad2[MAXN * HH];
// CSR scratch
__device__ int g_deg [MAXN];
__device__ int g_rp  [MAXN + 1];
__device__ int g_cur [MAXN];
__device__ int g_csr [MAXE];
__device__ int g_is64;
// decoupled-lookback scan state
__device__ int g_flag[128];
__device__ int g_agg [128];
__device__ int g_pref[128];

// ---------------- helpers ----------------------------------------------------
__device__ __forceinline__ int load_dst(const void* ei, long long t, long long E) {
    if (g_is64) return (int)((const long long*)ei)[E + t];
    return ((const int*)ei)[E + t];
}
__device__ __forceinline__ int load_src(const void* ei, long long t) {
    if (g_is64) return (int)((const long long*)ei)[t];
    return ((const int*)ei)[t];
}

// Blackwell packed f32x2 FMA (ptxas only emits FFMA2 via PTX fma.rn.f32x2)
__device__ __forceinline__ ull pack2(float x) {
    ull r; asm("mov.b64 %0, {%1, %1};" : "=l"(r) : "f"(x)); return r;
}
__device__ __forceinline__ void ffma2(ull& d, ull a, ull b) {
    asm("fma.rn.f32x2 %0, %1, %2, %0;" : "+l"(d) : "l"(a), "l"(b));
}
__device__ __forceinline__ float2 unpack2(ull v) {
    float lo, hi; asm("mov.b64 {%0, %1}, %2;" : "=f"(lo), "=f"(hi) : "l"(v));
    return make_float2(lo, hi);
}
__device__ __forceinline__ float lrelu_exp(float v) {
    float e = v > 0.f ? v : 0.2f * v;
    return __expf(e);
}

// ---------------- CSR build ---------------------------------------------------

// Detect int64 vs int32 + zero degree array + zero scan flags (fused).
__global__ void k_init(const unsigned* __restrict__ ei, int n) {
    int i = blockIdx.x * blockDim.x + threadIdx.x;
    if (i == 0) {
        int zeros = 0;
        for (int j = 0; j < 64; j++)
            if (ei[2 * j + 1] == 0u) zeros++;
        g_is64 = (zeros >= 60) ? 1 : 0;
    }
    if (i < 128) g_flag[i] = 0;
    if (i < n) g_deg[i] = 0;
}

// Heterogeneous kernel: first gtiles blocks run gemm1 (64x64 tile, FFMA2),
// remaining blocks histogram edge destinations (hidden behind the gemm).
__global__ void __launch_bounds__(256) k_gemm1_hist(
        const float* __restrict__ x, const float* __restrict__ W1,
        const float* __restrict__ asrc, const float* __restrict__ adst, int n,
        const void* __restrict__ ei, long long E, int gtiles) {
    if ((int)blockIdx.x >= gtiles) {
        long long t = (long long)(blockIdx.x - gtiles) * 256 + threadIdx.x;
        if (t < E) atomicAdd(&g_deg[load_dst(ei, t, E)], 1);
        return;
    }
    __shared__ __align__(16) float Ws[DIN * D1];   // [k][col] 32 KB
    __shared__ __align__(16) float xs[64][132];    // padded: banks rotate, f4-aligned
    __shared__ float av[2][D1];
    int tid = threadIdx.x;
    for (int i = tid; i < DIN * D1 / 4; i += 256)
        *(float4*)(Ws + 4 * i) = *(const float4*)(W1 + 4 * i);
    if (tid < D1) { av[0][tid] = asrc[tid]; av[1][tid] = adst[tid]; }

    int n0 = blockIdx.x * 64;
    for (int i = tid; i < 64 * 32; i += 256) {
        int r = i >> 5, c4 = i & 31;
        int nd = n0 + r;
        float4 v = (nd < n) ? *(const float4*)(x + (size_t)nd * DIN + 4 * c4)
                            : make_float4(0.f, 0.f, 0.f, 0.f);
        *(float4*)&xs[r][4 * c4] = v;
    }
    __syncthreads();

    int cg = tid & 15, rg = tid >> 4;
    int c0 = cg * 4, r0 = rg * 4;
    ull acc[4][2] = {};
    #pragma unroll 8
    for (int k = 0; k < DIN; k++) {
        ulonglong2 w = *(const ulonglong2*)(Ws + k * D1 + c0);
        #pragma unroll
        for (int i = 0; i < 4; i++) {
            ull xp = pack2(xs[r0 + i][k]);
            ffma2(acc[i][0], xp, w.x);
            ffma2(acc[i][1], xp, w.y);
        }
    }

    float h[4][4];
    #pragma unroll
    for (int i = 0; i < 4; i++) {
        float2 lo = unpack2(acc[i][0]), hi = unpack2(acc[i][1]);
        h[i][0] = lo.x; h[i][1] = lo.y; h[i][2] = hi.x; h[i][3] = hi.y;
    }
    float ps[4], pd[4];
    #pragma unroll
    for (int i = 0; i < 4; i++) {
        float s = 0.f, d = 0.f;
        #pragma unroll
        for (int j = 0; j < 4; j++) {
            s += h[i][j] * av[0][c0 + j];
            d += h[i][j] * av[1][c0 + j];
        }
        ps[i] = s; pd[i] = d;
    }
    #pragma unroll
    for (int i = 0; i < 4; i++) {
        ps[i] += __shfl_xor_sync(0xffffffffu, ps[i], 1);
        pd[i] += __shfl_xor_sync(0xffffffffu, pd[i], 1);
    }
    #pragma unroll
    for (int i = 0; i < 4; i++) {
        int nd = n0 + r0 + i;
        if (nd < n) {
            *(float4*)(g_h1 + (size_t)nd * D1 + c0) =
                make_float4(h[i][0], h[i][1], h[i][2], h[i][3]);
            if (!(cg & 1))
                { g_as1[(size_t)nd * 8 + (cg >> 1)] = ps[i];
                  g_ad1[(size_t)nd * 8 + (cg >> 1)] = pd[i]; }
        }
    }
}

// Single-pass decoupled-lookback scan of g_deg -> g_rp/g_cur.
__global__ void __launch_bounds__(1024) k_scan(int n, int E) {
    __shared__ int s[1024];
    __shared__ int s_run;
    int b = blockIdx.x;
    int i = b * 1024 + threadIdx.x;
    int v = (i < n) ? g_deg[i] : 0;
    s[threadIdx.x] = v;
    __syncthreads();
    #pragma unroll
    for (int off = 1; off < 1024; off <<= 1) {
        int t = (threadIdx.x >= off) ? s[threadIdx.x - off] : 0;
        __syncthreads();
        s[threadIdx.x] += t;
        __syncthreads();
    }
    int total = s[1023];

    if (threadIdx.x == 0) {
        if (b == 0) {
            g_pref[0] = total;
            __threadfence();
            g_flag[0] = 2;
            s_run = 0;
            g_rp[n] = E;
        } else {
            g_agg[b] = total;
            __threadfence();
            g_flag[b] = 1;
            int run = 0, p = b - 1;
            while (true) {
                int f;
                do { f = *(volatile int*)&g_flag[p]; } while (f == 0);
                __threadfence();
                if (f == 2) { run += *(volatile int*)&g_pref[p]; break; }
                run += *(volatile int*)&g_agg[p];
                p--;
            }
            g_pref[b] = run + total;
            __threadfence();
            g_flag[b] = 2;
            s_run = run;
        }
    }
    __syncthreads();
    if (i < n) {
        int e = s_run + s[threadIdx.x] - v;   // exclusive prefix
        g_rp[i] = e;
        g_cur[i] = e;
    }
}

__global__ void k_scatter(const void* __restrict__ ei, long long E) {
    long long t = (long long)blockIdx.x * blockDim.x + threadIdx.x;
    if (t >= E) return;
    int s = load_src(ei, t);
    int d = load_dst(ei, t, E);
    int pos = atomicAdd(&g_cur[d], 1);
    g_csr[pos] = s;
}

// ---------------- layer-2 GEMM + fused alpha2 ----------------------------------

// h2 = z1 @ W2, tile 64 nodes x 80 cols; thread = 4 rows x 4 cols (320 threads).
// Mainloop identical to the validated 320-thread version; epilogue additionally
// computes alpha_s2/alpha_d2 from an smem h tile (kills k_alpha2 + h2 re-read).
__global__ void __launch_bounds__(320) k_gemm2(
        const float* __restrict__ W2,
        const float* __restrict__ asrc, const float* __restrict__ adst, int n) {
    __shared__ __align__(16) float Ws[D1 * D2];    // 20 KB
    __shared__ __align__(16) float zs[64][68];     // 17.4 KB
    __shared__ __align__(16) float hs[64][80];     // 20 KB
    __shared__ float avs[D2], avd[D2];
    int tid = threadIdx.x;
    for (int i = tid; i < D1 * D2 / 4; i += 320)
        *(float4*)(Ws + 4 * i) = *(const float4*)(W2 + 4 * i);
    if (tid < D2) { avs[tid] = asrc[tid]; avd[tid] = adst[tid]; }
    int n0 = blockIdx.x * 64;
    for (int i = tid; i < 64 * 16; i += 320) {
        int r = i >> 4, c4 = i & 15;
        int nd = n0 + r;
        float4 v = (nd < n) ? *(const float4*)(g_z1 + (size_t)nd * D1 + 4 * c4)
                            : make_float4(0.f, 0.f, 0.f, 0.f);
        *(float4*)&zs[r][4 * c4] = v;
    }
    __syncthreads();

    int cg = tid % 20, rg = tid / 20;
    int c0 = cg * 4, r0 = rg * 4;
    ull acc[4][2] = {};
    #pragma unroll 8
    for (int k = 0; k < D1; k++) {
        ulonglong2 w = *(const ulonglong2*)(Ws + k * D2 + c0);
        #pragma unroll
        for (int i = 0; i < 4; i++) {
            ull xp = pack2(zs[r0 + i][k]);
            ffma2(acc[i][0], xp, w.x);
            ffma2(acc[i][1], xp, w.y);
        }
    }
    #pragma unroll
    for (int i = 0; i < 4; i++) {
        int r = r0 + i;
        int nd = n0 + r;
        float2 lo = unpack2(acc[i][0]), hi = unpack2(acc[i][1]);
        float4 hv = make_float4(lo.x, lo.y, hi.x, hi.y);
        *(float4*)&hs[r][c0] = hv;
        if (nd < n)
            *(float4*)(g_h2 + (size_t)nd * D2 + c0) = hv;
    }
    __syncthreads();

    // alpha epilogue: 64 rows x 8 heads = 512 tasks
    for (int t = tid; t < 512; t += 320) {
        int r = t >> 3, hd = t & 7;
        int nd = n0 + r;
        if (nd >= n) continue;
        float s = 0.f, d = 0.f;
        #pragma unroll
        for (int c = 0; c < 10; c++) {
            float v = hs[r][hd * 10 + c];
            s += v * avs[hd * 10 + c];
            d += v * avd[hd * 10 + c];
        }
        g_as2[(size_t)nd * 8 + hd] = s;
        g_ad2[(size_t)nd * 8 + hd] = d;
    }
}

// ---------------- CSR aggregation (warp per node, no atomics) ------------------
// Softmax without max-shift: exp(e)/sum(exp(e)) — safe, |logits| ~ O(1).
// Weight phase: 2 lanes per edge (even lane = alpha[0:4], odd = alpha[4:8] of the
// SAME edge) -> one coalesced wavefront per edge instead of two.

__global__ void k_agg1(const float* __restrict__ b1, int n) {
    __shared__ float wbuf[8][32][8];   // 8 KB
    __shared__ int   sbuf[8][32];      // 1 KB
    __shared__ float dbuf[8][8];
    int wid  = (blockIdx.x * blockDim.x + threadIdx.x) >> 5;
    int lane = threadIdx.x & 31;
    int wl   = threadIdx.x >> 5;
    if (wid >= n) return;
    int start = g_rp[wid], deg = g_rp[wid + 1] - start;
    int total = deg + 1;   // + self-loop
    int half = lane & 1;
    float4 adh = *(const float4*)(g_ad1 + (size_t)wid * 8 + half * 4);
    float4 den4 = make_float4(0.f, 0.f, 0.f, 0.f);
    float acc0 = 0.f, acc1 = 0.f;
    int head = lane >> 2;              // head of channels 2*lane, 2*lane+1
    for (int c0 = 0; c0 < total; c0 += 32) {
        int cnt = min(32, total - c0);
        #pragma unroll
        for (int j = 0; j < 2; j++) {
            int eo = j * 16 + (lane >> 1);
            int ew = c0 + eo;
            if (eo < cnt) {
                int s = (ew < deg) ? g_csr[start + ew] : wid;
                if (!half) sbuf[wl][eo] = s;
                float4 a = *(const float4*)(g_as1 + (size_t)s * 8 + half * 4);
                float4 w4;
                w4.x = lrelu_exp(a.x + adh.x);
                w4.y = lrelu_exp(a.y + adh.y);
                w4.z = lrelu_exp(a.z + adh.z);
                w4.w = lrelu_exp(a.w + adh.w);
                den4.x += w4.x; den4.y += w4.y; den4.z += w4.z; den4.w += w4.w;
                *(float4*)&wbuf[wl][eo][half * 4] = w4;
            }
        }
        __syncwarp();
        #pragma unroll 8
        for (int k = 0; k < cnt; k++) {
            int s = sbuf[wl][k];
            float2 hv = *(const float2*)(g_h1 + (size_t)s * D1 + 2 * lane);
            float w = wbuf[wl][k][head];
            acc0 += hv.x * w;
            acc1 += hv.y * w;
        }
        __syncwarp();
    }
    // den: xor offsets 16..2 preserve parity; even lanes hold heads 0-3, odd 4-7
    #pragma unroll
    for (int o = 16; o >= 2; o >>= 1) {
        den4.x += __shfl_xor_sync(0xffffffffu, den4.x, o);
        den4.y += __shfl_xor_sync(0xffffffffu, den4.y, o);
        den4.z += __shfl_xor_sync(0xffffffffu, den4.z, o);
        den4.w += __shfl_xor_sync(0xffffffffu, den4.w, o);
    }
    if (lane < 2) *(float4*)&dbuf[wl][half * 4] = den4;
    __syncwarp();
    float inv = 1.f / dbuf[wl][head];
    float v0 = acc0 * inv + b1[2 * lane];
    float v1 = acc1 * inv + b1[2 * lane + 1];
    v0 = v0 > 0.f ? v0 : expm1f(v0);
    v1 = v1 > 0.f ? v1 : expm1f(v1);
    *(float2*)(g_z1 + (size_t)wid * D1 + 2 * lane) = make_float2(v0, v1);
}

// Layer-2 aggregation + mean-over-heads + bias + log_softmax, fused.
__global__ void k_agg2(const float* __restrict__ b2, float* __restrict__ out, int n) {
    __shared__ float wbuf[8][32][8];
    __shared__ int   sbuf[8][32];
    __shared__ float dbuf[8][8];
    __shared__ float fb[8][80];
    int wid  = (blockIdx.x * blockDim.x + threadIdx.x) >> 5;
    int lane = threadIdx.x & 31;
    int wl   = threadIdx.x >> 5;
    if (wid >= n) return;
    int start = g_rp[wid], deg = g_rp[wid + 1] - start;
    int total = deg + 1;
    int half = lane & 1;
    float4 adh = *(const float4*)(g_ad2 + (size_t)wid * 8 + half * 4);
    float4 den4 = make_float4(0.f, 0.f, 0.f, 0.f);
    float acc0 = 0.f, acc1 = 0.f, acc2 = 0.f;
    int ha = (2 * lane) / 10;          // head of channels 2*lane, 2*lane+1
    int hc = (64 + lane) / 10;         // head of channel 64+lane (lane<16)
    for (int c0 = 0; c0 < total; c0 += 32) {
        int cnt = min(32, total - c0);
        #pragma unroll
        for (int j = 0; j < 2; j++) {
            int eo = j * 16 + (lane >> 1);
            int ew = c0 + eo;
            if (eo < cnt) {
                int s = (ew < deg) ? g_csr[start + ew] : wid;
                if (!half) sbuf[wl][eo] = s;
                float4 a = *(const float4*)(g_as2 + (size_t)s * 8 + half * 4);
                float4 w4;
                w4.x = lrelu_exp(a.x + adh.x);
                w4.y = lrelu_exp(a.y + adh.y);
                w4.z = lrelu_exp(a.z + adh.z);
                w4.w = lrelu_exp(a.w + adh.w);
                den4.x += w4.x; den4.y += w4.y; den4.z += w4.z; den4.w += w4.w;
                *(float4*)&wbuf[wl][eo][half * 4] = w4;
            }
        }
        __syncwarp();
        #pragma unroll 8
        for (int k = 0; k < cnt; k++) {
            int s = sbuf[wl][k];
            const float* hrow = g_h2 + (size_t)s * D2;
            float2 hv = *(const float2*)(hrow + 2 * lane);
            float wa = wbuf[wl][k][ha];
            acc0 += hv.x * wa;
            acc1 += hv.y * wa;
            if (lane < 16) {
                float hv2 = hrow[64 + lane];
                acc2 += hv2 * wbuf[wl][k][hc];
            }
        }
        __syncwarp();
    }
    #pragma unroll
    for (int o = 16; o >= 2; o >>= 1) {
        den4.x += __shfl_xor_sync(0xffffffffu, den4.x, o);
        den4.y += __shfl_xor_sync(0xffffffffu, den4.y, o);
        den4.z += __shfl_xor_sync(0xffffffffu, den4.z, o);
        den4.w += __shfl_xor_sync(0xffffffffu, den4.w, o);
    }
    if (lane < 2) *(float4*)&dbuf[wl][half * 4] = den4;
    __syncwarp();

    // scaled messages -> smem
    float inv_a = 1.f / dbuf[wl][ha];
    fb[wl][2 * lane]     = acc0 * inv_a;
    fb[wl][2 * lane + 1] = acc1 * inv_a;
    if (lane < 16) fb[wl][64 + lane] = acc2 / dbuf[wl][hc];
    __syncwarp();

    // mean over heads + bias + log_softmax (classes on lanes 0..9)
    float mval = -1e30f, mcls = 0.f;
    if (lane < 10) {
        float s = 0.f;
        #pragma unroll
        for (int h = 0; h < 8; h++) s += fb[wl][h * 10 + lane];
        mcls = s * 0.125f + b2[lane];
        mval = mcls;
    }
    #pragma unroll
    for (int o = 8; o >= 1; o >>= 1)
        mval = fmaxf(mval, __shfl_down_sync(0xffffffffu, mval, o));
    float mx = __shfl_sync(0xffffffffu, mval, 0);
    float ev = (lane < 10) ? __expf(mcls - mx) : 0.f;
    #pragma unroll
    for (int o = 8; o >= 1; o >>= 1)
        ev += __shfl_down_sync(0xffffffffu, ev, o);
    float lse = mx + __logf(__shfl_sync(0xffffffffu, ev, 0));
    if (lane < 10) out[(size_t)wid * 10 + lane] = mcls - lse;
}

// ---------------- launch ------------------------------------------------------
extern "C" void kernel_launch(void* const* d_in, const int* in_sizes, int n_in,
                              void* d_out, int out_size) {
    const float* x     = (const float*)d_in[0];
    const void*  ei    = d_in[1];
    const float* W1    = (const float*)d_in[2];
    const float* asrc1 = (const float*)d_in[3];
    const float* adst1 = (const float*)d_in[4];
    const float* b1    = (const float*)d_in[5];
    const float* W2    = (const float*)d_in[6];
    const float* asrc2 = (const float*)d_in[7];
    const float* adst2 = (const float*)d_in[8];
    const float* b2    = (const float*)d_in[9];
    float* out = (float*)d_out;

    int n = in_sizes[0] / DIN;                 // 100000
    long long E = (long long)in_sizes[1] / 2;  // 1600000
    int eb = (int)((E + 255) / 256);
    int nb = (n + 1023) / 1024;
    int tiles = (n + 63) / 64;

    // CSR build (+ gemm1 hidden behind hist)
    k_init<<<(n + 255) / 256, 256>>>((const unsigned*)ei, n);
    k_gemm1_hist<<<tiles + eb, 256>>>(x, W1, asrc1, adst1, n, ei, E, tiles);
    k_scan<<<nb, 1024>>>(n, (int)E);
    k_scatter<<<eb, 256>>>(ei, E);

    // Layer 1
    k_agg1<<<(n + 7) / 8, 256>>>(b1, n);

    // Layer 2 (alpha2 fused into gemm2)
    k_gemm2<<<tiles, 320>>>(W2, asrc2, adst2, n);
    k_agg2<<<(n + 7) / 8, 256>>>(b2, out, n);
}

// round 17
// speedup vs baseline: 1.0074x; 1.0055x over previous
#include <cuda_runtime.h>
#include <cstdint>
#include <limits.h>

// Problem constants (fixed by the dataset)
#define MAXN 100000
#define MAXE 1600000
#define DIN  128
#define HH   8
#define D1   64   // H*C1
#define D2   80   // H*C2

typedef unsigned long long ull;

// ---------------- scratch (device globals; no allocation allowed) -------------
__device__ __align__(16) float g_h1 [MAXN * D1];
__device__ __align__(16) float g_as1[MAXN * HH];
__device__ __align__(16) float g_ad1[MAXN * HH];
__device__ __align__(16) float g_z1 [MAXN * D1];
__device__ __align__(16) float g_h2 [MAXN * D2];
__device__ __align__(16) float g_as2[MAXN * HH];
__device__ __align__(16) float g_ad2[MAXN * HH];
// CSR scratch
__device__ int g_deg [MAXN];
__device__ int g_rp  [MAXN + 1];
__device__ int g_cur [MAXN];
__device__ int g_csr [MAXE];
__device__ int g_is64;
// decoupled-lookback scan state
__device__ int g_flag[128];
__device__ int g_agg [128];
__device__ int g_pref[128];

// ---------------- helpers ----------------------------------------------------
__device__ __forceinline__ int load_dst(const void* ei, long long t, long long E) {
    if (g_is64) return (int)((const long long*)ei)[E + t];
    return ((const int*)ei)[E + t];
}
__device__ __forceinline__ int load_src(const void* ei, long long t) {
    if (g_is64) return (int)((const long long*)ei)[t];
    return ((const int*)ei)[t];
}

// Blackwell packed f32x2 FMA (ptxas only emits FFMA2 via PTX fma.rn.f32x2)
__device__ __forceinline__ ull pack2(float x) {
    ull r; asm("mov.b64 %0, {%1, %1};" : "=l"(r) : "f"(x)); return r;
}
__device__ __forceinline__ void ffma2(ull& d, ull a, ull b) {
    asm("fma.rn.f32x2 %0, %1, %2, %0;" : "+l"(d) : "l"(a), "l"(b));
}
__device__ __forceinline__ float2 unpack2(ull v) {
    float lo, hi; asm("mov.b64 {%0, %1}, %2;" : "=f"(lo), "=f"(hi) : "l"(v));
    return make_float2(lo, hi);
}
__device__ __forceinline__ float lrelu_exp(float v) {
    float e = v > 0.f ? v : 0.2f * v;
    return __expf(e);
}

// ---------------- CSR build ---------------------------------------------------

// Detect int64 vs int32 + zero degree array + zero scan flags (fused).
__global__ void k_init(const unsigned* __restrict__ ei, int n) {
    int i = blockIdx.x * blockDim.x + threadIdx.x;
    if (i == 0) {
        int zeros = 0;
        for (int j = 0; j < 64; j++)
            if (ei[2 * j + 1] == 0u) zeros++;
        g_is64 = (zeros >= 60) ? 1 : 0;
    }
    if (i < 128) g_flag[i] = 0;
    if (i < n) g_deg[i] = 0;
}

// Heterogeneous kernel: first gtiles blocks run gemm1 (64x64 tile, FFMA2),
// remaining blocks histogram edge destinations (hidden behind the gemm).
__global__ void __launch_bounds__(256) k_gemm1_hist(
        const float* __restrict__ x, const float* __restrict__ W1,
        const float* __restrict__ asrc, const float* __restrict__ adst, int n,
        const void* __restrict__ ei, long long E, int gtiles) {
    if ((int)blockIdx.x >= gtiles) {
        long long t = (long long)(blockIdx.x - gtiles) * 256 + threadIdx.x;
        if (t < E) atomicAdd(&g_deg[load_dst(ei, t, E)], 1);
        return;
    }
    __shared__ __align__(16) float Ws[DIN * D1];   // [k][col] 32 KB
    __shared__ __align__(16) float xs[64][132];    // padded: banks rotate, f4-aligned
    __shared__ float av[2][D1];
    int tid = threadIdx.x;
    for (int i = tid; i < DIN * D1 / 4; i += 256)
        *(float4*)(Ws + 4 * i) = *(const float4*)(W1 + 4 * i);
    if (tid < D1) { av[0][tid] = asrc[tid]; av[1][tid] = adst[tid]; }

    int n0 = blockIdx.x * 64;
    for (int i = tid; i < 64 * 32; i += 256) {
        int r = i >> 5, c4 = i & 31;
        int nd = n0 + r;
        float4 v = (nd < n) ? *(const float4*)(x + (size_t)nd * DIN + 4 * c4)
                            : make_float4(0.f, 0.f, 0.f, 0.f);
        *(float4*)&xs[r][4 * c4] = v;
    }
    __syncthreads();

    int cg = tid & 15, rg = tid >> 4;
    int c0 = cg * 4, r0 = rg * 4;
    ull acc[4][2] = {};
    #pragma unroll 8
    for (int k = 0; k < DIN; k++) {
        ulonglong2 w = *(const ulonglong2*)(Ws + k * D1 + c0);
        #pragma unroll
        for (int i = 0; i < 4; i++) {
            ull xp = pack2(xs[r0 + i][k]);
            ffma2(acc[i][0], xp, w.x);
            ffma2(acc[i][1], xp, w.y);
        }
    }

    float h[4][4];
    #pragma unroll
    for (int i = 0; i < 4; i++) {
        float2 lo = unpack2(acc[i][0]), hi = unpack2(acc[i][1]);
        h[i][0] = lo.x; h[i][1] = lo.y; h[i][2] = hi.x; h[i][3] = hi.y;
    }
    float ps[4], pd[4];
    #pragma unroll
    for (int i = 0; i < 4; i++) {
        float s = 0.f, d = 0.f;
        #pragma unroll
        for (int j = 0; j < 4; j++) {
            s += h[i][j] * av[0][c0 + j];
            d += h[i][j] * av[1][c0 + j];
        }
        ps[i] = s; pd[i] = d;
    }
    #pragma unroll
    for (int i = 0; i < 4; i++) {
        ps[i] += __shfl_xor_sync(0xffffffffu, ps[i], 1);
        pd[i] += __shfl_xor_sync(0xffffffffu, pd[i], 1);
    }
    #pragma unroll
    for (int i = 0; i < 4; i++) {
        int nd = n0 + r0 + i;
        if (nd < n) {
            *(float4*)(g_h1 + (size_t)nd * D1 + c0) =
                make_float4(h[i][0], h[i][1], h[i][2], h[i][3]);
            if (!(cg & 1))
                { g_as1[(size_t)nd * 8 + (cg >> 1)] = ps[i];
                  g_ad1[(size_t)nd * 8 + (cg >> 1)] = pd[i]; }
        }
    }
}

// Single-pass decoupled-lookback scan of g_deg -> g_rp/g_cur.
__global__ void __launch_bounds__(1024) k_scan(int n, int E) {
    __shared__ int s[1024];
    __shared__ int s_run;
    int b = blockIdx.x;
    int i = b * 1024 + threadIdx.x;
    int v = (i < n) ? g_deg[i] : 0;
    s[threadIdx.x] = v;
    __syncthreads();
    #pragma unroll
    for (int off = 1; off < 1024; off <<= 1) {
        int t = (threadIdx.x >= off) ? s[threadIdx.x - off] : 0;
        __syncthreads();
        s[threadIdx.x] += t;
        __syncthreads();
    }
    int total = s[1023];

    if (threadIdx.x == 0) {
        if (b == 0) {
            g_pref[0] = total;
            __threadfence();
            g_flag[0] = 2;
            s_run = 0;
            g_rp[n] = E;
        } else {
            g_agg[b] = total;
            __threadfence();
            g_flag[b] = 1;
            int run = 0, p = b - 1;
            while (true) {
                int f;
                do { f = *(volatile int*)&g_flag[p]; } while (f == 0);
                __threadfence();
                if (f == 2) { run += *(volatile int*)&g_pref[p]; break; }
                run += *(volatile int*)&g_agg[p];
                p--;
            }
            g_pref[b] = run + total;
            __threadfence();
            g_flag[b] = 2;
            s_run = run;
        }
    }
    __syncthreads();
    if (i < n) {
        int e = s_run + s[threadIdx.x] - v;   // exclusive prefix
        g_rp[i] = e;
        g_cur[i] = e;
    }
}

__global__ void k_scatter(const void* __restrict__ ei, long long E) {
    long long t = (long long)blockIdx.x * blockDim.x + threadIdx.x;
    if (t >= E) return;
    int s = load_src(ei, t);
    int d = load_dst(ei, t, E);
    int pos = atomicAdd(&g_cur[d], 1);
    g_csr[pos] = s;
}

// ---------------- layer-2 GEMM + fused alpha2 ----------------------------------

// h2 = z1 @ W2, tile 64 nodes x 80 cols; thread = 4 rows x 4 cols (320 threads).
// Mainloop identical to the validated 320-thread version; epilogue additionally
// computes alpha_s2/alpha_d2 from an smem h tile (kills k_alpha2 + h2 re-read).
__global__ void __launch_bounds__(320) k_gemm2(
        const float* __restrict__ W2,
        const float* __restrict__ asrc, const float* __restrict__ adst, int n) {
    __shared__ __align__(16) float Ws[D1 * D2];    // 20 KB
    __shared__ __align__(16) float zs[64][68];     // 17.4 KB
    __shared__ __align__(16) float hs[64][80];     // 20 KB
    __shared__ float avs[D2], avd[D2];
    int tid = threadIdx.x;
    for (int i = tid; i < D1 * D2 / 4; i += 320)
        *(float4*)(Ws + 4 * i) = *(const float4*)(W2 + 4 * i);
    if (tid < D2) { avs[tid] = asrc[tid]; avd[tid] = adst[tid]; }
    int n0 = blockIdx.x * 64;
    for (int i = tid; i < 64 * 16; i += 320) {
        int r = i >> 4, c4 = i & 15;
        int nd = n0 + r;
        float4 v = (nd < n) ? *(const float4*)(g_z1 + (size_t)nd * D1 + 4 * c4)
                            : make_float4(0.f, 0.f, 0.f, 0.f);
        *(float4*)&zs[r][4 * c4] = v;
    }
    __syncthreads();

    int cg = tid % 20, rg = tid / 20;
    int c0 = cg * 4, r0 = rg * 4;
    ull acc[4][2] = {};
    #pragma unroll 8
    for (int k = 0; k < D1; k++) {
        ulonglong2 w = *(const ulonglong2*)(Ws + k * D2 + c0);
        #pragma unroll
        for (int i = 0; i < 4; i++) {
            ull xp = pack2(zs[r0 + i][k]);
            ffma2(acc[i][0], xp, w.x);
            ffma2(acc[i][1], xp, w.y);
        }
    }
    #pragma unroll
    for (int i = 0; i < 4; i++) {
        int r = r0 + i;
        int nd = n0 + r;
        float2 lo = unpack2(acc[i][0]), hi = unpack2(acc[i][1]);
        float4 hv = make_float4(lo.x, lo.y, hi.x, hi.y);
        *(float4*)&hs[r][c0] = hv;
        if (nd < n)
            *(float4*)(g_h2 + (size_t)nd * D2 + c0) = hv;
    }
    __syncthreads();

    // alpha epilogue: 64 rows x 8 heads = 512 tasks
    for (int t = tid; t < 512; t += 320) {
        int r = t >> 3, hd = t & 7;
        int nd = n0 + r;
        if (nd >= n) continue;
        float s = 0.f, d = 0.f;
        #pragma unroll
        for (int c = 0; c < 10; c++) {
            float v = hs[r][hd * 10 + c];
            s += v * avs[hd * 10 + c];
            d += v * avd[hd * 10 + c];
        }
        g_as2[(size_t)nd * 8 + hd] = s;
        g_ad2[(size_t)nd * 8 + hd] = d;
    }
}

// ---------------- CSR aggregation (warp per node, no atomics) ------------------
// Softmax without max-shift: exp(e)/sum(exp(e)) — safe, |logits| ~ O(1).
// Weight phase: 2 lanes per edge (even lane = alpha[0:4], odd = alpha[4:8] of the
// SAME edge) -> one coalesced wavefront per edge instead of two.

__global__ void k_agg1(const float* __restrict__ b1, int n) {
    __shared__ float wbuf[8][32][8];   // 8 KB
    __shared__ int   sbuf[8][32];      // 1 KB
    __shared__ float dbuf[8][8];
    int wid  = (blockIdx.x * blockDim.x + threadIdx.x) >> 5;
    int lane = threadIdx.x & 31;
    int wl   = threadIdx.x >> 5;
    if (wid >= n) return;
    int start = g_rp[wid], deg = g_rp[wid + 1] - start;
    int total = deg + 1;   // + self-loop
    int half = lane & 1;
    float4 adh = *(const float4*)(g_ad1 + (size_t)wid * 8 + half * 4);
    float4 den4 = make_float4(0.f, 0.f, 0.f, 0.f);
    float acc0 = 0.f, acc1 = 0.f;
    int head = lane >> 2;              // head of channels 2*lane, 2*lane+1
    for (int c0 = 0; c0 < total; c0 += 32) {
        int cnt = min(32, total - c0);
        #pragma unroll
        for (int j = 0; j < 2; j++) {
            int eo = j * 16 + (lane >> 1);
            int ew = c0 + eo;
            if (eo < cnt) {
                int s = (ew < deg) ? g_csr[start + ew] : wid;
                if (!half) sbuf[wl][eo] = s;
                float4 a = *(const float4*)(g_as1 + (size_t)s * 8 + half * 4);
                float4 w4;
                w4.x = lrelu_exp(a.x + adh.x);
                w4.y = lrelu_exp(a.y + adh.y);
                w4.z = lrelu_exp(a.z + adh.z);
                w4.w = lrelu_exp(a.w + adh.w);
                den4.x += w4.x; den4.y += w4.y; den4.z += w4.z; den4.w += w4.w;
                *(float4*)&wbuf[wl][eo][half * 4] = w4;
            }
        }
        __syncwarp();
        #pragma unroll 8
        for (int k = 0; k < cnt; k++) {
            int s = sbuf[wl][k];
            float2 hv = *(const float2*)(g_h1 + (size_t)s * D1 + 2 * lane);
            float w = wbuf[wl][k][head];
            acc0 += hv.x * w;
            acc1 += hv.y * w;
        }
        __syncwarp();
    }
    // den: xor offsets 16..2 preserve parity; even lanes hold heads 0-3, odd 4-7
    #pragma unroll
    for (int o = 16; o >= 2; o >>= 1) {
        den4.x += __shfl_xor_sync(0xffffffffu, den4.x, o);
        den4.y += __shfl_xor_sync(0xffffffffu, den4.y, o);
        den4.z += __shfl_xor_sync(0xffffffffu, den4.z, o);
        den4.w += __shfl_xor_sync(0xffffffffu, den4.w, o);
    }
    if (lane < 2) *(float4*)&dbuf[wl][half * 4] = den4;
    __syncwarp();
    float inv = 1.f / dbuf[wl][head];
    float v0 = acc0 * inv + b1[2 * lane];
    float v1 = acc1 * inv + b1[2 * lane + 1];
    v0 = v0 > 0.f ? v0 : expm1f(v0);
    v1 = v1 > 0.f ? v1 : expm1f(v1);
    *(float2*)(g_z1 + (size_t)wid * D1 + 2 * lane) = make_float2(v0, v1);
}

// Layer-2 aggregation + mean-over-heads + bias + log_softmax, fused.
__global__ void k_agg2(const float* __restrict__ b2, float* __restrict__ out, int n) {
    __shared__ float wbuf[8][32][8];
    __shared__ int   sbuf[8][32];
    __shared__ float dbuf[8][8];
    __shared__ float fb[8][80];
    int wid  = (blockIdx.x * blockDim.x + threadIdx.x) >> 5;
    int lane = threadIdx.x & 31;
    int wl   = threadIdx.x >> 5;
    if (wid >= n) return;
    int start = g_rp[wid], deg = g_rp[wid + 1] - start;
    int total = deg + 1;
    int half = lane & 1;
    float4 adh = *(const float4*)(g_ad2 + (size_t)wid * 8 + half * 4);
    float4 den4 = make_float4(0.f, 0.f, 0.f, 0.f);
    float acc0 = 0.f, acc1 = 0.f, acc2 = 0.f;
    int ha = (2 * lane) / 10;          // head of channels 2*lane, 2*lane+1
    int hc = (64 + lane) / 10;         // head of channel 64+lane (lane<16)
    for (int c0 = 0; c0 < total; c0 += 32) {
        int cnt = min(32, total - c0);
        #pragma unroll
        for (int j = 0; j < 2; j++) {
            int eo = j * 16 + (lane >> 1);
            int ew = c0 + eo;
            if (eo < cnt) {
                int s = (ew < deg) ? g_csr[start + ew] : wid;
                if (!half) sbuf[wl][eo] = s;
                float4 a = *(const float4*)(g_as2 + (size_t)s * 8 + half * 4);
                float4 w4;
                w4.x = lrelu_exp(a.x + adh.x);
                w4.y = lrelu_exp(a.y + adh.y);
                w4.z = lrelu_exp(a.z + adh.z);
                w4.w = lrelu_exp(a.w + adh.w);
                den4.x += w4.x; den4.y += w4.y; den4.z += w4.z; den4.w += w4.w;
                *(float4*)&wbuf[wl][eo][half * 4] = w4;
            }
        }
        __syncwarp();
        #pragma unroll 8
        for (int k = 0; k < cnt; k++) {
            int s = sbuf[wl][k];
            const float* hrow = g_h2 + (size_t)s * D2;
            float2 hv = *(const float2*)(hrow + 2 * lane);
            float wa = wbuf[wl][k][ha];
            acc0 += hv.x * wa;
            acc1 += hv.y * wa;
            if (lane < 16) {
                float hv2 = hrow[64 + lane];
                acc2 += hv2 * wbuf[wl][k][hc];
            }
        }
        __syncwarp();
    }
    #pragma unroll
    for (int o = 16; o >= 2; o >>= 1) {
        den4.x += __shfl_xor_sync(0xffffffffu, den4.x, o);
        den4.y += __shfl_xor_sync(0xffffffffu, den4.y, o);
        den4.z += __shfl_xor_sync(0xffffffffu, den4.z, o);
        den4.w += __shfl_xor_sync(0xffffffffu, den4.w, o);
    }
    if (lane < 2) *(float4*)&dbuf[wl][half * 4] = den4;
    __syncwarp();

    // scaled messages -> smem
    float inv_a = 1.f / dbuf[wl][ha];
    fb[wl][2 * lane]     = acc0 * inv_a;
    fb[wl][2 * lane + 1] = acc1 * inv_a;
    if (lane < 16) fb[wl][64 + lane] = acc2 / dbuf[wl][hc];
    __syncwarp();

    // mean over heads + bias + log_softmax (classes on lanes 0..9)
    float mval = -1e30f, mcls = 0.f;
    if (lane < 10) {
        float s = 0.f;
        #pragma unroll
        for (int h = 0; h < 8; h++) s += fb[wl][h * 10 + lane];
        mcls = s * 0.125f + b2[lane];
        mval = mcls;
    }
    #pragma unroll
    for (int o = 8; o >= 1; o >>= 1)
        mval = fmaxf(mval, __shfl_down_sync(0xffffffffu, mval, o));
    float mx = __shfl_sync(0xffffffffu, mval, 0);
    float ev = (lane < 10) ? __expf(mcls - mx) : 0.f;
    #pragma unroll
    for (int o = 8; o >= 1; o >>= 1)
        ev += __shfl_down_sync(0xffffffffu, ev, o);
    float lse = mx + __logf(__shfl_sync(0xffffffffu, ev, 0));
    if (lane < 10) out[(size_t)wid * 10 + lane] = mcls - lse;
}

// ---------------- launch ------------------------------------------------------
extern "C" void kernel_launch(void* const* d_in, const int* in_sizes, int n_in,
                              void* d_out, int out_size) {
    const float* x     = (const float*)d_in[0];
    const void*  ei    = d_in[1];
    const float* W1    = (const float*)d_in[2];
    const float* asrc1 = (const float*)d_in[3];
    const float* adst1 = (const float*)d_in[4];
    const float* b1    = (const float*)d_in[5];
    const float* W2    = (const float*)d_in[6];
    const float* asrc2 = (const float*)d_in[7];
    const float* adst2 = (const float*)d_in[8];
    const float* b2    = (const float*)d_in[9];
    float* out = (float*)d_out;

    int n = in_sizes[0] / DIN;                 // 100000
    long long E = (long long)in_sizes[1] / 2;  // 1600000
    int eb = (int)((E + 255) / 256);
    int nb = (n + 1023) / 1024;
    int tiles = (n + 63) / 64;

    // CSR build (+ gemm1 hidden behind hist)
    k_init<<<(n + 255) / 256, 256>>>((const unsigned*)ei, n);
    k_gemm1_hist<<<tiles + eb, 256>>>(x, W1, asrc1, adst1, n, ei, E, tiles);
    k_scan<<<nb, 1024>>>(n, (int)E);
    k_scatter<<<eb, 256>>>(ei, E);

    // Layer 1
    k_agg1<<<(n + 7) / 8, 256>>>(b1, n);

    // Layer 2 (alpha2 fused into gemm2)
    k_gemm2<<<tiles, 320>>>(W2, asrc2, adst2, n);
    k_agg2<<<(n + 7) / 8, 256>>>(b2, out, n);
}